// round 9
// baseline (speedup 1.0000x reference)
#include <cuda_runtime.h>
#include <cuda_bf16.h>

// Problem constants (fixed by setup_inputs): B=2, C=16, H=W=256, Cctx=64, Cqk=2, Cv=1
#define BB   2
#define CC   16
#define HH   256
#define WW   256
#define CTX  64
#define HW   (HH * WW)          // 65536
#define HW4  (HW / 4)           // 16384
#define LOG2E 1.4426950408889634f

// Scratch (all L2-resident):
__device__ float2 g_K01[BB * HW];
__device__ float  g_V  [BB * HW];
__device__ float2 g_Q01[BB * HW];
__device__ float2 g_part[2][BB * HW];

// ---------------------------------------------------------------------------
// Kernel 1: fused Q, K, V projections. Cooperative channel-split:
// 4 threads (s = tid&3) share one float4 position-group. Each thread loads
// 4/16 x-channels and 16/64 y-channels (20 LDG.128, all independent), then a
// 2-round shfl_xor butterfly (s lives in lane bits 0..1) reduces the partial
// q/k/v accumulators. Lane s==0 adds biases, scales q by log2(e), writes.
// 131072 threads -> 512 CTAs; launch_bounds(256,4) keeps regs <= 64 so both
// occupancy AND per-thread load pipelining stay high (bytes-in-flight fix
// for the R8 regression).
// ---------------------------------------------------------------------------
__global__ void __launch_bounds__(256, 4) proj_kernel(
    const float* __restrict__ x, const float* __restrict__ y,
    const float* __restrict__ Wq, const float* __restrict__ bq,
    const float* __restrict__ Wk, const float* __restrict__ bk,
    const float* __restrict__ Wv, const float* __restrict__ bv)
{
    const int tid = blockIdx.x * 256 + threadIdx.x;   // [0, 4*BB*HW4) = 131072
    const int g   = tid >> 2;                         // float4 pos-group [0, 32768)
    const int s   = tid & 3;                          // channel split
    const int b   = g >> 14;                          // g / HW4
    const int p4  = g & (HW4 - 1);

    float4 k0 = make_float4(0.f, 0.f, 0.f, 0.f);
    float4 k1 = make_float4(0.f, 0.f, 0.f, 0.f);
    float4 q0 = make_float4(0.f, 0.f, 0.f, 0.f);
    float4 q1 = make_float4(0.f, 0.f, 0.f, 0.f);
    float4 v  = make_float4(0.f, 0.f, 0.f, 0.f);

    const float4* xb = (const float4*)x + (size_t)b * CC * HW4 + p4;
#pragma unroll
    for (int i = 0; i < 4; i++) {
        int c = s * 4 + i;
        float4 xv = __ldg(xb + c * HW4);
        float wk0 = __ldg(Wk + c), wk1 = __ldg(Wk + CC + c);
        float wq0 = __ldg(Wq + c), wq1 = __ldg(Wq + CC + c);
        k0.x = fmaf(wk0, xv.x, k0.x); k0.y = fmaf(wk0, xv.y, k0.y);
        k0.z = fmaf(wk0, xv.z, k0.z); k0.w = fmaf(wk0, xv.w, k0.w);
        k1.x = fmaf(wk1, xv.x, k1.x); k1.y = fmaf(wk1, xv.y, k1.y);
        k1.z = fmaf(wk1, xv.z, k1.z); k1.w = fmaf(wk1, xv.w, k1.w);
        q0.x = fmaf(wq0, xv.x, q0.x); q0.y = fmaf(wq0, xv.y, q0.y);
        q0.z = fmaf(wq0, xv.z, q0.z); q0.w = fmaf(wq0, xv.w, q0.w);
        q1.x = fmaf(wq1, xv.x, q1.x); q1.y = fmaf(wq1, xv.y, q1.y);
        q1.z = fmaf(wq1, xv.z, q1.z); q1.w = fmaf(wq1, xv.w, q1.w);
    }

    const float4* yb = (const float4*)y + (size_t)b * CTX * HW4 + p4;
#pragma unroll
    for (int i = 0; i < 16; i++) {
        int c = s * 16 + i;
        float4 yv = __ldg(yb + c * HW4);
        float wv  = __ldg(Wv + c);
        v.x = fmaf(wv, yv.x, v.x); v.y = fmaf(wv, yv.y, v.y);
        v.z = fmaf(wv, yv.z, v.z); v.w = fmaf(wv, yv.w, v.w);
    }

    // Butterfly reduction across the 4 channel-splits (lane bits 0..1).
#define RED4(f) \
    f += __shfl_xor_sync(0xffffffffu, f, 1); \
    f += __shfl_xor_sync(0xffffffffu, f, 2);
    RED4(k0.x) RED4(k0.y) RED4(k0.z) RED4(k0.w)
    RED4(k1.x) RED4(k1.y) RED4(k1.z) RED4(k1.w)
    RED4(q0.x) RED4(q0.y) RED4(q0.z) RED4(q0.w)
    RED4(q1.x) RED4(q1.y) RED4(q1.z) RED4(q1.w)
    RED4(v.x)  RED4(v.y)  RED4(v.z)  RED4(v.w)
#undef RED4

    if (s == 0) {
        float bk0 = __ldg(bk + 0), bk1 = __ldg(bk + 1);
        float bq0 = __ldg(bq + 0), bq1 = __ldg(bq + 1);
        float bv0 = __ldg(bv);

        float4* K01o = (float4*)g_K01 + (size_t)g * 2;
        K01o[0] = make_float4(k0.x + bk0, k1.x + bk1, k0.y + bk0, k1.y + bk1);
        K01o[1] = make_float4(k0.z + bk0, k1.z + bk1, k0.w + bk0, k1.w + bk1);

        float4* Q01o = (float4*)g_Q01 + (size_t)g * 2;
        Q01o[0] = make_float4((q0.x + bq0) * LOG2E, (q1.x + bq1) * LOG2E,
                              (q0.y + bq0) * LOG2E, (q1.y + bq1) * LOG2E);
        Q01o[1] = make_float4((q0.z + bq0) * LOG2E, (q1.z + bq1) * LOG2E,
                              (q0.w + bq0) * LOG2E, (q1.w + bq1) * LOG2E);

        ((float4*)g_V)[g] = make_float4(v.x + bv0, v.y + bv0, v.z + bv0, v.w + bv0);
    }
}

// ---------------------------------------------------------------------------
// Kernel 2: split-g partial attention (unchanged — near its MUFU floor).
// ---------------------------------------------------------------------------
__global__ void __launch_bounds__(512, 4) attn_partial_kernel(void)
{
    __shared__ float2 sK[2][128];
    __shared__ float  sV[2][128];

    const int tid    = threadIdx.x;
    const int r      = tid >> 8;             // h-row within CTA (0/1)
    const int w      = tid & (WW - 1);

    const int split  = blockIdx.x & 1;
    const int rowblk = blockIdx.x >> 1;      // [0, B*H/2)
    const int b      = rowblk >> 7;
    const int h      = ((rowblk & 127) << 1) + r;
    const int g0     = split << 7;           // 0 or 128

    const int plane = b * HW;
    const int pos   = plane + h * WW + w;

    if (w < 128) {
        int rp = plane + h * WW + g0 + w;
        sK[r][w] = g_K01[rp];
        sV[r][w] = g_V [rp];
    }

    const float2 q = g_Q01[pos];
    __syncthreads();

    const float2* Kc = g_K01 + plane + g0 * WW + w;   // column walk, coalesced
    const float*  Vc = g_V   + plane + g0 * WW + w;

    float s   = 0.0f;
    float acc = 0.0f;

#pragma unroll 4
    for (int j = 0; j < 128; j++) {
        float2 kc = Kc[j * WW];
        float  vc = Vc[j * WW];
        float  e  = fmaf(q.x, kc.x, q.y * kc.y);
        float  pe;
        asm("ex2.approx.f32 %0, %1;" : "=f"(pe) : "f"(e));
        s   += pe;
        acc  = fmaf(pe, vc, acc);

        float2 kr = sK[r][j];
        float  vr = sV[r][j];
        float  e2 = fmaf(q.x, kr.x, q.y * kr.y);
        float  pe2;
        asm("ex2.approx.f32 %0, %1;" : "=f"(pe2) : "f"(e2));
        s   += pe2;
        acc  = fmaf(pe2, vr, acc);
    }

    // Subtract the masked diagonal term (g == h) if it fell in this split.
    if ((unsigned)(h - g0) < 128u) {
        float2 kd = g_K01[pos];
        float  vd = g_V [pos];
        float  ed = fmaf(q.x, kd.x, q.y * kd.y);
        float  pd;
        asm("ex2.approx.f32 %0, %1;" : "=f"(pd) : "f"(ed));
        s   -= pd;
        acc  = fmaf(-pd, vd, acc);
    }

    g_part[split][pos] = make_float2(s, acc);
}

// ---------------------------------------------------------------------------
// Kernel 3: combine partials, float4-vectorized (4 positions/thread).
// ---------------------------------------------------------------------------
__global__ void __launch_bounds__(256) combine_kernel(
    const float* __restrict__ x,
    const float* __restrict__ gamma,
    float* __restrict__ out)
{
    int idx = blockIdx.x * 256 + threadIdx.x;      // [0, BB*HW4)
    int b   = idx >> 14;
    int p4  = idx & (HW4 - 1);

    const float4* pp0 = (const float4*)g_part[0] + (size_t)idx * 2;
    const float4* pp1 = (const float4*)g_part[1] + (size_t)idx * 2;
    float4 a00 = pp0[0], a01 = pp0[1];
    float4 a10 = pp1[0], a11 = pp1[1];

    float g = __ldg(gamma);
    float4 res;
    res.x = g * (a00.y + a10.y) / (a00.x + a10.x);
    res.y = g * (a00.w + a10.w) / (a00.z + a10.z);
    res.z = g * (a01.y + a11.y) / (a01.x + a11.x);
    res.w = g * (a01.w + a11.w) / (a01.z + a11.z);

    const float4* xb = (const float4*)x   + (size_t)b * CC * HW4 + p4;
    float4*       ob = (float4*)out       + (size_t)b * CC * HW4 + p4;
#pragma unroll
    for (int c = 0; c < CC; c++) {
        float4 xv = __ldg(xb + c * HW4);
        ob[c * HW4] = make_float4(res.x + xv.x, res.y + xv.y,
                                  res.z + xv.z, res.w + xv.w);
    }
}

// ---------------------------------------------------------------------------
// kernel_launch: inputs per metadata order:
//   0:x (B,C,H,W) 1:y (B,64,H,W) 2:Wq (2,16) 3:bq (2) 4:Wk (2,16) 5:bk (2)
//   6:Wv (1,64)  7:bv (1)        8:gamma (1)
// ---------------------------------------------------------------------------
extern "C" void kernel_launch(void* const* d_in, const int* in_sizes, int n_in,
                              void* d_out, int out_size)
{
    const float* x     = (const float*)d_in[0];
    const float* y     = (const float*)d_in[1];
    const float* Wq    = (const float*)d_in[2];
    const float* bq    = (const float*)d_in[3];
    const float* Wk    = (const float*)d_in[4];
    const float* bk    = (const float*)d_in[5];
    const float* Wv    = (const float*)d_in[6];
    const float* bv    = (const float*)d_in[7];
    const float* gamma = (const float*)d_in[8];
    float* out = (float*)d_out;

    proj_kernel<<<(4 * BB * HW4) / 256, 256>>>(x, y, Wq, bq, Wk, bk, Wv, bv);
    attn_partial_kernel<<<BB * HH, 512>>>();
    combine_kernel<<<(BB * HW4) / 256, 256>>>(x, gamma, out);
}